// round 11
// baseline (speedup 1.0000x reference)
#include <cuda_runtime.h>

#define NFEAT 262144
#define NTGT  8192
#define NLAT  32
#define NB    128
#define NTH   512
#define FB4   (NFEAT/NB/4)   /* 512 float4 per block = 1 per thread */
#define YF4   (NTGT/4)       /* 2048 float4 total target vector     */
#define YSL4  (YF4/NB)       /* 16 float4 block slice (threads 0-15)*/
#define EPSV  1e-7f

/* output offsets (floats) */
#define OFF_MUY  (NFEAT)
#define OFF_U    (NFEAT + NTGT)
#define OFF_WZ   (OFF_U + NLAT)
#define OFF_CZ   (OFF_WZ + NLAT*NFEAT)
#define OFF_TSS  (OFF_CZ + NLAT*NTGT)
#define OFF_BZ   (OFF_TSS + NLAT)
#define OFF_P    (OFF_BZ + NLAT)

/* mailbox: NLAT slots x NB blocks x 3 float4 (11 dots + sig word) */
__device__ float4   g_part[NLAT*NB*3];
__device__ unsigned g_sig[NB];   /* per-launch epoch base only */

static __device__ __forceinline__ unsigned ld_acq(const unsigned* p){
  unsigned v;
  asm volatile("ld.acquire.gpu.global.u32 %0, [%1];" : "=r"(v) : "l"(p) : "memory");
  return v;
}
static __device__ __forceinline__ void st_rel(unsigned* p, unsigned v){
  asm volatile("st.release.gpu.global.u32 [%0], %1;" :: "l"(p), "r"(v) : "memory");
}
static __device__ __forceinline__ float4 ldcg4(const float4* p){
  float4 v;
  asm volatile("ld.global.cg.v4.f32 {%0,%1,%2,%3}, [%4];"
               : "=f"(v.x),"=f"(v.y),"=f"(v.z),"=f"(v.w) : "l"(p) : "memory");
  return v;
}
static __device__ __forceinline__ void stcg4(float4* p, float4 v){
  asm volatile("st.global.cg.v4.f32 [%0], {%1,%2,%3,%4};"
               :: "l"(p),"f"(v.x),"f"(v.y),"f"(v.z),"f"(v.w) : "memory");
}
static __device__ __forceinline__ void stcg1(float* p, float v){
  asm volatile("st.global.cg.f32 [%0], %1;" :: "l"(p), "f"(v) : "memory");
}
static __device__ __forceinline__ void npause(){
  asm volatile("nanosleep.u32 40;");
}

static __device__ __forceinline__ float d4(float4 a, float4 b){
  return fmaf(a.x,b.x, fmaf(a.y,b.y, fmaf(a.z,b.z, a.w*b.w)));
}
static __device__ __forceinline__ float4 f4fma(float4 a, float s, float4 b){
  float4 r; r.x=fmaf(a.x,s,b.x); r.y=fmaf(a.y,s,b.y);
  r.z=fmaf(a.z,s,b.z); r.w=fmaf(a.w,s,b.w); return r;
}
static __device__ __forceinline__ void f4add(float4& a, float4 b){
  a.x+=b.x; a.y+=b.y; a.z+=b.z; a.w+=b.w;
}

#define SHFL8(mask,o) do{                            \
    a.x += __shfl_xor_sync(mask,a.x,o);              \
    a.y += __shfl_xor_sync(mask,a.y,o);              \
    a.z += __shfl_xor_sync(mask,a.z,o);              \
    a.w += __shfl_xor_sync(mask,a.w,o);              \
    b.x += __shfl_xor_sync(mask,b.x,o);              \
    b.y += __shfl_xor_sync(mask,b.y,o);              \
    b.z += __shfl_xor_sync(mask,b.z,o);              \
    b.w += __shfl_xor_sync(mask,b.w,o);              \
  }while(0)
#define SHFL11(mask,o) do{                           \
    a.x += __shfl_xor_sync(mask,a.x,o);              \
    a.y += __shfl_xor_sync(mask,a.y,o);              \
    a.z += __shfl_xor_sync(mask,a.z,o);              \
    a.w += __shfl_xor_sync(mask,a.w,o);              \
    b.x += __shfl_xor_sync(mask,b.x,o);              \
    b.y += __shfl_xor_sync(mask,b.y,o);              \
    b.z += __shfl_xor_sync(mask,b.z,o);              \
    b.w += __shfl_xor_sync(mask,b.w,o);              \
    c.x += __shfl_xor_sync(mask,c.x,o);              \
    c.y += __shfl_xor_sync(mask,c.y,o);              \
    c.z += __shfl_xor_sync(mask,c.z,o);              \
  }while(0)

/* posted slot layout (12 floats): [0..3]=a (feature), [4..7]=b.xyz + target0,
   [8..10]=targets 1..3, [11]=sig word (unsigned, st.release) */
static __device__ __forceinline__ void post_sig(int slot, int bid,
                                                float4 a, float4 b, float4 c,
                                                unsigned sig){
  float* mp = (float*)&g_part[(slot*NB + bid)*3];
  stcg4((float4*)mp,     a);
  stcg4((float4*)mp + 1, b);
  stcg1(mp+8,  c.x); stcg1(mp+9, c.y); stcg1(mp+10, c.z);
  st_rel((unsigned*)(mp+11), sig);
}

/* full bred + post (prologue/burn-in use; ONE syncthreads inside) */
static __device__ __forceinline__ void bred_post(int slot, int bid, unsigned sig,
                                                 float4 a, float4 b, float4 t,
                                                 float4* s_wA){
  #pragma unroll
  for (int o=16;o>0;o>>=1) SHFL8(0xffffffffu,o);
  int w = threadIdx.x >> 5;
  if ((threadIdx.x & 31) == 0){ s_wA[w]=a; s_wA[16+w]=b; }
  __syncthreads();
  if (threadIdx.x < 32){
    float4 z = make_float4(0.f,0.f,0.f,0.f);
    int l = threadIdx.x;
    a = (l<16) ? s_wA[l]    : z;
    b = (l<16) ? s_wA[16+l] : z;
    #pragma unroll
    for (int o=16;o>0;o>>=1) SHFL8(0xffffffffu,o);
    if (threadIdx.x == 0){
      b.w = t.x;
      post_sig(slot, bid, a, b, make_float4(t.y,t.z,t.w,0.f), sig);
    }
  }
}

/* reduce 4 target floats over warp0 lanes 0-15 (call only from tid<16) */
static __device__ __forceinline__ float4 tred16(float4 t){
  #pragma unroll
  for (int o=8;o>0;o>>=1){
    t.x += __shfl_xor_sync(0x0000ffffu,t.x,o);
    t.y += __shfl_xor_sync(0x0000ffffu,t.y,o);
    t.z += __shfl_xor_sync(0x0000ffffu,t.z,o);
    t.w += __shfl_xor_sync(0x0000ffffu,t.w,o);
  }
  return t;
}

/* standalone gather (prologue/burn-in use; TWO syncthreads inside) */
static __device__ __forceinline__ void gather11(int slot, unsigned sigval,
                                                float4& A, float4& B, float4& C,
                                                float4* s_wB){
  __syncthreads();
  if (threadIdx.x < NB){
    const float* mp = (const float*)&g_part[(slot*NB + threadIdx.x)*3];
    while (ld_acq((const unsigned*)(mp+11)) < sigval) npause();
    float4 a = ldcg4((const float4*)mp);
    float4 b = ldcg4((const float4*)mp + 1);
    float4 c = ldcg4((const float4*)mp + 2);
    #pragma unroll
    for (int o=16;o>0;o>>=1) SHFL11(0xffffffffu,o);
    if ((threadIdx.x & 31) == 0){
      int w = threadIdx.x >> 5;
      s_wB[w]=a; s_wB[4+w]=b; s_wB[8+w]=c;
    }
  }
  __syncthreads();
  float4 a = s_wB[0], b = s_wB[4], c = s_wB[8];
  #pragma unroll
  for (int i=1;i<4;i++){
    f4add(a, s_wB[i]); f4add(b, s_wB[4+i]);
    c.x += s_wB[8+i].x; c.y += s_wB[8+i].y; c.z += s_wB[8+i].z;
  }
  A=a; B=b; C=c;
}

__global__ void __launch_bounds__(NTH, 1)
ipls_kernel(const float* __restrict__ x,      const float* __restrict__ y,
            const float* __restrict__ mux,    const float* __restrict__ muy,
            const float* __restrict__ u_in,   const float* __restrict__ Wz_in,
            const float* __restrict__ Cz_in,  const float* __restrict__ tss_in,
            const float* __restrict__ bz_in,  const float* __restrict__ P_in,
            const int* __restrict__ n_in,     float* __restrict__ out)
{
  __shared__ float4 s_wA[32];
  __shared__ float4 s_wB[12];

  const int tid = threadIdx.x, bid = blockIdx.x;
  const bool yown = (tid < YSL4);              /* warp 0, lanes 0-15 */
  const unsigned base = ld_acq(&g_sig[bid]);   /* uniform epoch base */

  const int n   = n_in[0];
  const float fn1  = (float)(n + 1);
  const float fden = (float)(n + 2);

  /* ---- init: feature slice in registers ---- */
  float4 xr;
  {
    int gi = bid*FB4 + tid;
    float4 xv = ((const float4*)x)[gi];
    float4 mv = ((const float4*)mux)[gi];
    float4 mu;
    mu.x = (mv.x*fn1 + xv.x)/fden; mu.y = (mv.y*fn1 + xv.y)/fden;
    mu.z = (mv.z*fn1 + xv.z)/fden; mu.w = (mv.w*fn1 + xv.w)/fden;
    ((float4*)out)[gi] = mu;
    xr.x = xv.x-mu.x; xr.y = xv.y-mu.y; xr.z = xv.z-mu.z; xr.w = xv.w-mu.w;
  }

  /* ---- init: target slice (threads 0-15 own 1 float4 each) ---- */
  float4 yrs = make_float4(0.f,0.f,0.f,0.f);
  if (yown){
    int gi = bid*YSL4 + tid;
    float4 yv = ((const float4*)y)[gi];
    float4 mv = ((const float4*)muy)[gi];
    float4 mu;
    mu.x = (mv.x*fn1 + yv.x)/fden; mu.y = (mv.y*fn1 + yv.y)/fden;
    mu.z = (mv.z*fn1 + yv.z)/fden; mu.w = (mv.w*fn1 + yv.w)/fden;
    ((float4*)(out + OFF_MUY))[gi] = mu;
    yrs.x = yv.x-mu.x; yrs.y = yv.y-mu.y; yrs.z = yv.z-mu.z; yrs.w = yv.w-mu.w;
  }

  /* prologue prefetch (distance 2 on W/Cz, 1 on P) */
  const float4* W4 = (const float4*)Wz_in;
  const float4* P4 = (const float4*)P_in;
  const float4* C4 = (const float4*)Cz_in;
  const int fidx = bid*FB4 + tid;
  float4 wcur   = ldcg4(W4 + fidx);
  float4 wnext  = ldcg4(W4 + (size_t)(NFEAT/4)   + fidx);
  float4 wnext2 = ldcg4(W4 + (size_t)2*(NFEAT/4) + fidx);
  float4 pc     = ldcg4(P4 + fidx);
  float4 pn1    = ldcg4(P4 + (size_t)(NFEAT/4)   + fidx);
  float4 czs0 = make_float4(0.f,0.f,0.f,0.f);
  float4 czs1 = czs0, czs2 = czs0;
  if (yown){
    czs0 = ldcg4(C4 + bid*YSL4 + tid);
    czs1 = ldcg4(C4 + YF4   + bid*YSL4 + tid);
    czs2 = ldcg4(C4 + 2*YF4 + bid*YSL4 + tid);
  }

  /* ---- burn-in path (n_new <= 3): only Wz and t_sq_sum change ---- */
  if (n + 1 <= 3){
    for (int c=0;c<NLAT;c++){
      float u_c = u_in[c];
      float4 w = (c==0) ? wcur : ((c==1) ? wnext : ((c==2) ? wnext2
               : ldcg4(W4 + (size_t)c*(NFEAT/4) + fidx)));
      float4 wz = f4fma(xr, u_c, w);
      stcg4(((float4*)(out + OFF_WZ)) + (size_t)c*(NFEAT/4) + fidx, wz);
      float4 a = make_float4(d4(xr,wz), d4(wz,wz), 0.f, 0.f);
      float4 b = make_float4(0.f,0.f,0.f,0.f);
      bred_post(c, bid, base + 1u + (unsigned)c, a, b, b, s_wA);
      __syncthreads();
    }

    if (bid == 0){
      for (int c=0;c<NLAT;c++){
        float4 ga, gb, gc;
        gather11(c, base + 1u + (unsigned)c, ga, gb, gc, s_wB);
        if (tid == 0){
          float tzb = ga.x / (sqrtf(ga.y) + EPSV);
          out[OFF_TSS + c] = tss_in[c] + tzb*tzb;
          out[OFF_U   + c] = u_in[c];
          out[OFF_BZ  + c] = bz_in[c];
        }
      }
    }
    int g = bid*NTH + tid;
    ((float4*)(out + OFF_CZ))[g] = ((const float4*)Cz_in)[g];
    #pragma unroll 4
    for (int k=0;k<(NLAT*NFEAT/4)/(NB*NTH);k++)
      ((float4*)(out + OFF_P))[k*NB*NTH + g] = P4[k*NB*NTH + g];
    __syncthreads();
    if (tid == 0) st_rel(&g_sig[bid], base + 1000u);
    return;
  }

  /* prologue post slot0: direct invariants of comp 0 */
  {
    float4 t = make_float4(0.f,0.f,0.f,0.f);
    if (yown)
      t = tred16(make_float4(d4(czs0,yrs), d4(czs0,czs0), d4(yrs,yrs), 0.f));
    float4 a = make_float4(d4(xr,wcur), d4(wcur,wcur), d4(xr,xr), 0.f);
    float4 b = make_float4(0.f,0.f,0.f,0.f);
    bred_post(0, bid, base + 1u, a, b, t, s_wA);
    __syncthreads();
  }
  /* prologue post slot1: raw-dot format for comp 1 (xr0 basis, no P_{-1}) */
  {
    float4 t = make_float4(0.f,0.f,0.f,0.f);
    if (yown)
      t = tred16(make_float4(d4(czs1,yrs), 0.f, d4(czs1,czs0), d4(czs1,czs1)));
    float4 a = make_float4(d4(xr,wnext), 0.f, d4(pc,wnext), d4(wnext,wnext));
    float4 b = make_float4(d4(xr,pc), 0.f, d4(pc,pc), 0.f);
    bred_post(1, bid, base + 2u, a, b, t, s_wA);
  }

  /* gather comp-0 invariants (A=a.x B=a.y Q=a.z F=b.w E=c.x G=c.y) */
  float A, B, Q, E, F, G;
  {
    float4 ga, gb, gc;
    gather11(0, base + 1u, ga, gb, gc, s_wB);
    A = ga.x; B = ga.y; Q = ga.z; F = gb.w; E = gc.x; G = gc.y;
  }
  float t_p = 0.f, dd_p = 1.f, ss_p = 1.f, kk_p = 0.f;

  /* ---- main scan: overlapped post/gather, 2 syncthreads per iter ---- */
  for (int c=0;c<NLAT;c++){
    const size_t frow = (size_t)c*(NFEAT/4) + fidx;
    const bool do_post   = (c+2 < NLAT);
    const bool do_gather = (c+1 < NLAT);

    /* post-path stage 1 for slot c+2 (all threads) */
    float4 tpost = make_float4(0.f,0.f,0.f,0.f);
    if (do_post){
      if (yown)
        tpost = tred16(make_float4(d4(czs2,yrs),  d4(czs2,czs0),
                                   d4(czs2,czs1), d4(czs2,czs2)));
      float4 a = make_float4(d4(xr,wnext2), d4(pc,wnext2),
                             d4(pn1,wnext2), d4(wnext2,wnext2));
      float4 b = make_float4(d4(xr,pn1), d4(pc,pn1), d4(pn1,pn1), 0.f);
      #pragma unroll
      for (int o=16;o>0;o>>=1) SHFL8(0xffffffffu,o);
      int w = tid >> 5;
      if ((tid & 31) == 0){ s_wA[w]=a; s_wA[16+w]=b; }
    }
    __syncthreads();                                      /* [1] */

    /* warp 0: post stage2+store.  warps 2-5: gather stage1 (concurrent) */
    if (tid < 32){
      if (do_post){
        float4 z = make_float4(0.f,0.f,0.f,0.f);
        int l = tid;
        float4 a = (l<16) ? s_wA[l]    : z;
        float4 b = (l<16) ? s_wA[16+l] : z;
        #pragma unroll
        for (int o=16;o>0;o>>=1) SHFL8(0xffffffffu,o);
        if (tid == 0){
          b.w = tpost.x;
          post_sig(c+2, bid, a, b,
                   make_float4(tpost.y,tpost.z,tpost.w,0.f),
                   base + 3u + (unsigned)c);
        }
      }
    } else if (tid >= 64 && tid < 64+NB){
      if (do_gather){
        const float* mp = (const float*)&g_part[((c+1)*NB + (tid-64))*3];
        while (ld_acq((const unsigned*)(mp+11)) < base + 2u + (unsigned)c)
          npause();
        float4 a = ldcg4((const float4*)mp);
        float4 b = ldcg4((const float4*)mp + 1);
        float4 c4v = ldcg4((const float4*)mp + 2);
        { float4 c = c4v;
          #pragma unroll
          for (int o=16;o>0;o>>=1) SHFL11(0xffffffffu,o);
          c4v = c;
          if ((tid & 31) == 0){
            int w = (tid-64) >> 5;
            s_wB[w]=a; s_wB[4+w]=b; s_wB[8+w]=c4v;
          }
        }
      }
    }
    __syncthreads();                                      /* [2] */

    /* final gather sum (all threads, 4 partials) */
    float4 ga, gb, gc;
    if (do_gather){
      ga = s_wB[0]; gb = s_wB[4]; gc = s_wB[8];
      #pragma unroll
      for (int i=1;i<4;i++){
        f4add(ga, s_wB[i]); f4add(gb, s_wB[4+i]);
        gc.x += s_wB[8+i].x; gc.y += s_wB[8+i].y; gc.z += s_wB[8+i].z;
      }
    }

    /* scalar chain for comp c */
    const float u0   = u_in[c];
    const float tss0 = tss_in[c];
    const float bz0  = bz_in[c];

    float tz1  = (A + u0*Q) / (sqrtf(fmaxf(B + 2.f*u0*A + u0*u0*Q, 0.f)) + EPSV);
    float tss1 = tss0 + tz1*tz1;
    float t1   = tz1 / sqrtf(tss1);
    float c21  = fmaxf(E + 2.f*t1*F + t1*t1*G, 0.f);
    float u1   = (F + t1*G) / sqrtf(c21);

    float tz   = (A + u1*Q) / (sqrtf(fmaxf(B + 2.f*u1*A + u1*u1*Q, 0.f)) + EPSV);
    float tss_ = tss0 + tz*tz;
    float t    = tz / sqrtf(tss_);
    float c2   = fmaxf(E + 2.f*t*F + t*t*G, 0.f);
    float rc2  = rsqrtf(c2);
    float u_f  = (F + t*G) * rc2;
    float bz_new = bz0 + u_f*tz;
    float bb   = bz_new / sqrtf(tss_);
    float kk   = bb * t * rc2;          /* b*t/||cz||           */
    float ss   = 1.f - kk*t;            /* yr' = ss*yr - kk*Cz  */
    float dd   = 1.f - t*t;             /* xr' = dd*xr - t*P_in */

    /* vector work (streams) */
    stcg4(((float4*)(out + OFF_WZ)) + frow, f4fma(xr, u1, wcur));

    if (yown){
      float4 czk = f4fma(yrs, t, czs0);
      stcg4(((float4*)(out + OFF_CZ)) + (size_t)c*YF4 + bid*YSL4 + tid, czk);
      yrs = f4fma(czk, -kk, yrs);
    }
    if (bid == 0 && tid == 0){
      out[OFF_U   + c] = u_f;
      out[OFF_TSS + c] = tss_;
      out[OFF_BZ  + c] = bz_new;
    }

    float4 pn = f4fma(xr, t, pc);
    stcg4(((float4*)(out + OFF_P)) + frow, pn);
    xr = f4fma(pn, -t, xr);

    float Gn = ss*ss*G - 2.f*ss*kk*F + kk*kk*E;

    /* shift + prefetch next operands */
    wcur = wnext; wnext = wnext2;
    if (c+3 < NLAT)
      wnext2 = ldcg4(W4 + (size_t)(c+3)*(NFEAT/4) + fidx);
    pc = pn1;
    if (c+2 < NLAT)
      pn1 = ldcg4(P4 + (size_t)(c+2)*(NFEAT/4) + fidx);
    czs0 = czs1; czs1 = czs2;
    if (yown && c+3 < NLAT)
      czs2 = ldcg4(C4 + (size_t)(c+3)*YF4 + bid*YSL4 + tid);
    else
      czs2 = make_float4(0.f,0.f,0.f,0.f);

    /* apply deflation algebra to gathered raw dots for comp c+1 */
    if (do_gather){
      A = dd*fmaf(dd_p, ga.x, -t_p*ga.y) - t*ga.z;
      B = ga.w;
      float xrP = fmaf(dd_p, gb.x, -t_p*gb.y);
      Q = dd*dd*Q - 2.f*t*dd*xrP + t*t*gb.z;
      F = ss*fmaf(ss_p, gb.w, -kk_p*gc.x) - kk*gc.y;
      E = gc.z;
      G = Gn;
      t_p = t; dd_p = dd; ss_p = ss; kk_p = kk;
    }
  }

  __syncthreads();
  if (tid == 0) st_rel(&g_sig[bid], base + 1000u);
}

extern "C" void kernel_launch(void* const* d_in, const int* in_sizes, int n_in,
                              void* d_out, int out_size)
{
  (void)in_sizes; (void)n_in; (void)out_size;
  ipls_kernel<<<NB, NTH>>>(
      (const float*)d_in[0],  (const float*)d_in[1],
      (const float*)d_in[2],  (const float*)d_in[3],
      (const float*)d_in[4],  (const float*)d_in[5],
      (const float*)d_in[6],  (const float*)d_in[7],
      (const float*)d_in[8],  (const float*)d_in[9],
      (const int*)  d_in[10], (float*)d_out);
}

// round 12
// speedup vs baseline: 1.2635x; 1.2635x over previous
#include <cuda_runtime.h>

#define NFEAT 262144
#define NTGT  8192
#define NLAT  32
#define NB    128
#define NC    512            /* compute threads */
#define NTH   544            /* + 1 comm warp  */
#define FB4   (NFEAT/NB/4)   /* 512 float4 per block = 1 per compute thread */
#define YF4   (NTGT/4)
#define YSL4  (YF4/NB)       /* 16 float4 block slice (threads 0-15) */
#define EPSV  1e-7f

#define OFF_MUY  (NFEAT)
#define OFF_U    (NFEAT + NTGT)
#define OFF_WZ   (OFF_U + NLAT)
#define OFF_CZ   (OFF_WZ + NLAT*NFEAT)
#define OFF_TSS  (OFF_CZ + NLAT*NTGT)
#define OFF_BZ   (OFF_TSS + NLAT)
#define OFF_P    (OFF_BZ + NLAT)

/* mailbox: NLAT slots x NB blocks x 3 float4 (11 dots + sig word) */
__device__ float4   g_part[NLAT*NB*3];
__device__ unsigned g_sig[NB];   /* per-launch epoch base only */

#define BAR1() asm volatile("bar.sync 1, 544;" ::: "memory")
#define BAR2() asm volatile("bar.sync 2, 544;" ::: "memory")

static __device__ __forceinline__ unsigned ld_acq(const unsigned* p){
  unsigned v;
  asm volatile("ld.acquire.gpu.global.u32 %0, [%1];" : "=r"(v) : "l"(p) : "memory");
  return v;
}
static __device__ __forceinline__ void st_rel(unsigned* p, unsigned v){
  asm volatile("st.release.gpu.global.u32 [%0], %1;" :: "l"(p), "r"(v) : "memory");
}
static __device__ __forceinline__ float4 ldcg4(const float4* p){
  float4 v;
  asm volatile("ld.global.cg.v4.f32 {%0,%1,%2,%3}, [%4];"
               : "=f"(v.x),"=f"(v.y),"=f"(v.z),"=f"(v.w) : "l"(p) : "memory");
  return v;
}
static __device__ __forceinline__ void stcg4(float4* p, float4 v){
  asm volatile("st.global.cg.v4.f32 [%0], {%1,%2,%3,%4};"
               :: "l"(p),"f"(v.x),"f"(v.y),"f"(v.z),"f"(v.w) : "memory");
}
static __device__ __forceinline__ void stcg1(float* p, float v){
  asm volatile("st.global.cg.f32 [%0], %1;" :: "l"(p), "f"(v) : "memory");
}
static __device__ __forceinline__ void npause(){
  asm volatile("nanosleep.u32 40;");
}

static __device__ __forceinline__ float d4(float4 a, float4 b){
  return fmaf(a.x,b.x, fmaf(a.y,b.y, fmaf(a.z,b.z, a.w*b.w)));
}
static __device__ __forceinline__ float4 f4fma(float4 a, float s, float4 b){
  float4 r; r.x=fmaf(a.x,s,b.x); r.y=fmaf(a.y,s,b.y);
  r.z=fmaf(a.z,s,b.z); r.w=fmaf(a.w,s,b.w); return r;
}
static __device__ __forceinline__ void f4add(float4& a, float4 b){
  a.x+=b.x; a.y+=b.y; a.z+=b.z; a.w+=b.w;
}

#define SHFL8(mask,o) do{                            \
    a.x += __shfl_xor_sync(mask,a.x,o);              \
    a.y += __shfl_xor_sync(mask,a.y,o);              \
    a.z += __shfl_xor_sync(mask,a.z,o);              \
    a.w += __shfl_xor_sync(mask,a.w,o);              \
    b.x += __shfl_xor_sync(mask,b.x,o);              \
    b.y += __shfl_xor_sync(mask,b.y,o);              \
    b.z += __shfl_xor_sync(mask,b.z,o);              \
    b.w += __shfl_xor_sync(mask,b.w,o);              \
  }while(0)
#define SHFL11S(o) do{                               \
    ga.x += __shfl_xor_sync(0xffffffffu,ga.x,o);     \
    ga.y += __shfl_xor_sync(0xffffffffu,ga.y,o);     \
    ga.z += __shfl_xor_sync(0xffffffffu,ga.z,o);     \
    ga.w += __shfl_xor_sync(0xffffffffu,ga.w,o);     \
    gb.x += __shfl_xor_sync(0xffffffffu,gb.x,o);     \
    gb.y += __shfl_xor_sync(0xffffffffu,gb.y,o);     \
    gb.z += __shfl_xor_sync(0xffffffffu,gb.z,o);     \
    gb.w += __shfl_xor_sync(0xffffffffu,gb.w,o);     \
    gc.x += __shfl_xor_sync(0xffffffffu,gc.x,o);     \
    gc.y += __shfl_xor_sync(0xffffffffu,gc.y,o);     \
    gc.z += __shfl_xor_sync(0xffffffffu,gc.z,o);     \
  }while(0)

/* posted slot: [0..3]=a, [4..7]=b(.w=target0), [8..10]=targets1..3, [11]=sig */
static __device__ __forceinline__ void post_sig(int slot, int bid,
                                                float4 a, float4 b, float4 c,
                                                unsigned sig){
  float* mp = (float*)&g_part[(slot*NB + bid)*3];
  stcg4((float4*)mp,     a);
  stcg4((float4*)mp + 1, b);
  stcg1(mp+8,  c.x); stcg1(mp+9, c.y); stcg1(mp+10, c.z);
  st_rel((unsigned*)(mp+11), sig);
}

/* full bred + post (prologue/burn-in; ONE __syncthreads inside).
   comm threads (tid>=NC) contribute nothing and don't write s_wA. */
static __device__ __forceinline__ void bred_post(int slot, int bid, unsigned sig,
                                                 float4 a, float4 b, float4 t,
                                                 float4* s_wA){
  #pragma unroll
  for (int o=16;o>0;o>>=1) SHFL8(0xffffffffu,o);
  int w = threadIdx.x >> 5;
  if ((threadIdx.x & 31) == 0 && threadIdx.x < NC){ s_wA[w]=a; s_wA[16+w]=b; }
  __syncthreads();
  if (threadIdx.x < 32){
    float4 z = make_float4(0.f,0.f,0.f,0.f);
    int l = threadIdx.x;
    a = (l<16) ? s_wA[l]    : z;
    b = (l<16) ? s_wA[16+l] : z;
    #pragma unroll
    for (int o=16;o>0;o>>=1) SHFL8(0xffffffffu,o);
    if (threadIdx.x == 0){
      b.w = t.x;
      post_sig(slot, bid, a, b, make_float4(t.y,t.z,t.w,0.f), sig);
    }
  }
}

static __device__ __forceinline__ float4 tred16(float4 t){
  #pragma unroll
  for (int o=8;o>0;o>>=1){
    t.x += __shfl_xor_sync(0x0000ffffu,t.x,o);
    t.y += __shfl_xor_sync(0x0000ffffu,t.y,o);
    t.z += __shfl_xor_sync(0x0000ffffu,t.z,o);
    t.w += __shfl_xor_sync(0x0000ffffu,t.w,o);
  }
  return t;
}

/* standalone gather (prologue/burn-in; TWO __syncthreads inside) */
static __device__ __forceinline__ void gather11(int slot, unsigned sigval,
                                                float4& A, float4& B, float4& C,
                                                float4* s_wB){
  __syncthreads();
  if (threadIdx.x < NB){
    const float* mp = (const float*)&g_part[(slot*NB + threadIdx.x)*3];
    while (ld_acq((const unsigned*)(mp+11)) < sigval) npause();
    float4 ga = ldcg4((const float4*)mp);
    float4 gb = ldcg4((const float4*)mp + 1);
    float4 gc = ldcg4((const float4*)mp + 2);
    #pragma unroll
    for (int o=16;o>0;o>>=1) SHFL11S(o);
    if ((threadIdx.x & 31) == 0){
      int w = threadIdx.x >> 5;
      s_wB[w]=ga; s_wB[4+w]=gb; s_wB[8+w]=gc;
    }
  }
  __syncthreads();
  float4 a = s_wB[0], b = s_wB[4], c = s_wB[8];
  #pragma unroll
  for (int i=1;i<4;i++){
    f4add(a, s_wB[i]); f4add(b, s_wB[4+i]);
    c.x += s_wB[8+i].x; c.y += s_wB[8+i].y; c.z += s_wB[8+i].z;
  }
  A=a; B=b; C=c;
}

__global__ void __launch_bounds__(NTH, 1)
ipls_kernel(const float* __restrict__ x,      const float* __restrict__ y,
            const float* __restrict__ mux,    const float* __restrict__ muy,
            const float* __restrict__ u_in,   const float* __restrict__ Wz_in,
            const float* __restrict__ Cz_in,  const float* __restrict__ tss_in,
            const float* __restrict__ bz_in,  const float* __restrict__ P_in,
            const int* __restrict__ n_in,     float* __restrict__ out)
{
  __shared__ float4 s_wA[32];
  __shared__ float4 s_wB[12];
  __shared__ float4 s_wT[1];

  const int tid = threadIdx.x, bid = blockIdx.x;
  const bool feat = (tid < NC);
  const bool yown = (tid < YSL4);              /* warp 0, lanes 0-15 */
  const unsigned base = ld_acq(&g_sig[bid]);   /* uniform epoch base */

  const int n   = n_in[0];
  const float fn1  = (float)(n + 1);
  const float fden = (float)(n + 2);

  const float4* W4 = (const float4*)Wz_in;
  const float4* P4 = (const float4*)P_in;
  const float4* C4 = (const float4*)Cz_in;
  const int fidx = bid*FB4 + tid;              /* valid only when feat */

  /* ---- init: feature slice + target slice + prefetch (compute only) ---- */
  float4 xr = make_float4(0.f,0.f,0.f,0.f);
  float4 yrs = xr, wcur = xr, wnext = xr, wnext2 = xr, pc = xr, pn1 = xr;
  float4 czs0 = xr, czs1 = xr, czs2 = xr;
  if (feat){
    float4 xv = ((const float4*)x)[fidx];
    float4 mv = ((const float4*)mux)[fidx];
    float4 mu;
    mu.x = (mv.x*fn1 + xv.x)/fden; mu.y = (mv.y*fn1 + xv.y)/fden;
    mu.z = (mv.z*fn1 + xv.z)/fden; mu.w = (mv.w*fn1 + xv.w)/fden;
    ((float4*)out)[fidx] = mu;
    xr.x = xv.x-mu.x; xr.y = xv.y-mu.y; xr.z = xv.z-mu.z; xr.w = xv.w-mu.w;

    wcur   = ldcg4(W4 + fidx);
    wnext  = ldcg4(W4 + (size_t)(NFEAT/4)   + fidx);
    wnext2 = ldcg4(W4 + (size_t)2*(NFEAT/4) + fidx);
    pc     = ldcg4(P4 + fidx);
    pn1    = ldcg4(P4 + (size_t)(NFEAT/4)   + fidx);
  }
  if (yown){
    int gi = bid*YSL4 + tid;
    float4 yv = ((const float4*)y)[gi];
    float4 mv = ((const float4*)muy)[gi];
    float4 mu;
    mu.x = (mv.x*fn1 + yv.x)/fden; mu.y = (mv.y*fn1 + yv.y)/fden;
    mu.z = (mv.z*fn1 + yv.z)/fden; mu.w = (mv.w*fn1 + yv.w)/fden;
    ((float4*)(out + OFF_MUY))[gi] = mu;
    yrs.x = yv.x-mu.x; yrs.y = yv.y-mu.y; yrs.z = yv.z-mu.z; yrs.w = yv.w-mu.w;
    czs0 = ldcg4(C4 + bid*YSL4 + tid);
    czs1 = ldcg4(C4 + YF4   + bid*YSL4 + tid);
    czs2 = ldcg4(C4 + 2*YF4 + bid*YSL4 + tid);
  }

  /* ---- burn-in path (n_new <= 3) ---- */
  if (n + 1 <= 3){
    for (int c=0;c<NLAT;c++){
      float4 a = make_float4(0.f,0.f,0.f,0.f);
      float4 b = a;
      if (feat){
        float u_c = u_in[c];
        float4 w = (c==0) ? wcur : ((c==1) ? wnext : ((c==2) ? wnext2
                 : ldcg4(W4 + (size_t)c*(NFEAT/4) + fidx)));
        float4 wz = f4fma(xr, u_c, w);
        stcg4(((float4*)(out + OFF_WZ)) + (size_t)c*(NFEAT/4) + fidx, wz);
        a = make_float4(d4(xr,wz), d4(wz,wz), 0.f, 0.f);
      }
      bred_post(c, bid, base + 1u + (unsigned)c, a, b, b, s_wA);
      __syncthreads();
    }

    if (bid == 0){
      for (int c=0;c<NLAT;c++){
        float4 ga, gb, gc;
        gather11(c, base + 1u + (unsigned)c, ga, gb, gc, s_wB);
        if (tid == 0){
          float tzb = ga.x / (sqrtf(ga.y) + EPSV);
          out[OFF_TSS + c] = tss_in[c] + tzb*tzb;
          out[OFF_U   + c] = u_in[c];
          out[OFF_BZ  + c] = bz_in[c];
        }
      }
    }
    if (feat){
      int g = bid*NC + tid;
      ((float4*)(out + OFF_CZ))[g] = ((const float4*)Cz_in)[g];
      #pragma unroll 4
      for (int k=0;k<(NLAT*NFEAT/4)/(NB*NC);k++)
        ((float4*)(out + OFF_P))[k*NB*NC + g] = P4[k*NB*NC + g];
    }
    __syncthreads();
    if (tid == 0) st_rel(&g_sig[bid], base + 1000u);
    return;
  }

  /* prologue post slot0: direct invariants of comp 0 */
  {
    float4 t = make_float4(0.f,0.f,0.f,0.f);
    if (yown)
      t = tred16(make_float4(d4(czs0,yrs), d4(czs0,czs0), d4(yrs,yrs), 0.f));
    float4 a = make_float4(0.f,0.f,0.f,0.f), b = a;
    if (feat) a = make_float4(d4(xr,wcur), d4(wcur,wcur), d4(xr,xr), 0.f);
    bred_post(0, bid, base + 1u, a, b, t, s_wA);
    __syncthreads();
  }
  /* prologue post slot1: raw-dot format for comp 1 (xr0 basis) */
  {
    float4 t = make_float4(0.f,0.f,0.f,0.f);
    if (yown)
      t = tred16(make_float4(d4(czs1,yrs), 0.f, d4(czs1,czs0), d4(czs1,czs1)));
    float4 a = make_float4(0.f,0.f,0.f,0.f), b = a;
    if (feat){
      a = make_float4(d4(xr,wnext), 0.f, d4(pc,wnext), d4(wnext,wnext));
      b = make_float4(d4(xr,pc), 0.f, d4(pc,pc), 0.f);
    }
    bred_post(1, bid, base + 2u, a, b, t, s_wA);
  }

  /* gather comp-0 invariants */
  float A, B, Q, E, F, G;
  {
    float4 ga, gb, gc;
    gather11(0, base + 1u, ga, gb, gc, s_wB);
    A = ga.x; B = ga.y; Q = ga.z; F = gb.w; E = gc.x; G = gc.y;
  }
  float t_p = 0.f, dd_p = 1.f, ss_p = 1.f, kk_p = 0.f;

  /* ---- main scan: comm-warp overlapped, 2 named barriers per iter ---- */
  for (int c=0;c<NLAT;c++){
    const bool do_post   = (c+2 < NLAT);
    const bool do_gather = (c+1 < NLAT);

    if (feat){
      const size_t frow = (size_t)c*(NFEAT/4) + fidx;

      /* stage-1 dots for slot c+2 (xr_c basis) + target handoff */
      if (do_post){
        if (yown){
          float4 tp = tred16(make_float4(d4(czs2,yrs),  d4(czs2,czs0),
                                         d4(czs2,czs1), d4(czs2,czs2)));
          if (tid == 0) s_wT[0] = tp;
        }
        float4 a = make_float4(d4(xr,wnext2), d4(pc,wnext2),
                               d4(pn1,wnext2), d4(wnext2,wnext2));
        float4 b = make_float4(d4(xr,pn1), d4(pc,pn1), d4(pn1,pn1), 0.f);
        #pragma unroll
        for (int o=16;o>0;o>>=1) SHFL8(0xffffffffu,o);
        int w = tid >> 5;
        if ((tid & 31) == 0){ s_wA[w]=a; s_wA[16+w]=b; }
      }
      BAR1();

      /* scalar chain comp c */
      const float u0   = u_in[c];
      const float tss0 = tss_in[c];
      const float bz0  = bz_in[c];

      float tz1  = (A + u0*Q) / (sqrtf(fmaxf(B + 2.f*u0*A + u0*u0*Q, 0.f)) + EPSV);
      float tss1 = tss0 + tz1*tz1;
      float t1   = tz1 / sqrtf(tss1);
      float c21  = fmaxf(E + 2.f*t1*F + t1*t1*G, 0.f);
      float u1   = (F + t1*G) / sqrtf(c21);

      float tz   = (A + u1*Q) / (sqrtf(fmaxf(B + 2.f*u1*A + u1*u1*Q, 0.f)) + EPSV);
      float tss_ = tss0 + tz*tz;
      float t    = tz / sqrtf(tss_);
      float c2   = fmaxf(E + 2.f*t*F + t*t*G, 0.f);
      float rc2  = rsqrtf(c2);
      float u_f  = (F + t*G) * rc2;
      float bz_new = bz0 + u_f*tz;
      float bb   = bz_new / sqrtf(tss_);
      float kk   = bb * t * rc2;
      float ss   = 1.f - kk*t;
      float dd   = 1.f - t*t;

      /* vector work */
      stcg4(((float4*)(out + OFF_WZ)) + frow, f4fma(xr, u1, wcur));
      if (yown){
        float4 czk = f4fma(yrs, t, czs0);
        stcg4(((float4*)(out + OFF_CZ)) + (size_t)c*YF4 + bid*YSL4 + tid, czk);
        yrs = f4fma(czk, -kk, yrs);
      }
      if (bid == 0 && tid == 0){
        out[OFF_U   + c] = u_f;
        out[OFF_TSS + c] = tss_;
        out[OFF_BZ  + c] = bz_new;
      }
      float4 pn = f4fma(xr, t, pc);
      stcg4(((float4*)(out + OFF_P)) + frow, pn);
      xr = f4fma(pn, -t, xr);

      float Gn = ss*ss*G - 2.f*ss*kk*F + kk*kk*E;

      /* shift + prefetch */
      wcur = wnext; wnext = wnext2;
      if (c+3 < NLAT)
        wnext2 = ldcg4(W4 + (size_t)(c+3)*(NFEAT/4) + fidx);
      pc = pn1;
      if (c+2 < NLAT)
        pn1 = ldcg4(P4 + (size_t)(c+2)*(NFEAT/4) + fidx);
      czs0 = czs1; czs1 = czs2;
      if (yown && c+3 < NLAT)
        czs2 = ldcg4(C4 + (size_t)(c+3)*YF4 + bid*YSL4 + tid);
      else
        czs2 = make_float4(0.f,0.f,0.f,0.f);

      BAR2();

      /* consume comm warp's gathered raw dots for comp c+1 */
      if (do_gather){
        float4 ga = s_wB[0], gb = s_wB[1], gc = s_wB[2];
        A = dd*fmaf(dd_p, ga.x, -t_p*ga.y) - t*ga.z;
        B = ga.w;
        float xrP = fmaf(dd_p, gb.x, -t_p*gb.y);
        Q = dd*dd*Q - 2.f*t*dd*xrP + t*t*gb.z;
        F = ss*fmaf(ss_p, gb.w, -kk_p*gc.x) - kk*gc.y;
        E = gc.z;
        G = Gn;
        t_p = t; dd_p = dd; ss_p = ss; kk_p = kk;
      }
    } else {
      /* ======== comm warp (tids 512-543) ======== */
      BAR1();
      if (do_post){
        float4 a, b;
        {
          float4 z = make_float4(0.f,0.f,0.f,0.f);
          int l = tid - NC;
          a = (l<16) ? s_wA[l]    : z;
          b = (l<16) ? s_wA[16+l] : z;
          #pragma unroll
          for (int o=16;o>0;o>>=1) SHFL8(0xffffffffu,o);
        }
        if (tid == NC){
          float4 tp = s_wT[0];
          b.w = tp.x;
          post_sig(c+2, bid, a, b, make_float4(tp.y,tp.z,tp.w,0.f),
                   base + 3u + (unsigned)c);
        }
      }
      if (do_gather){
        const int l = tid - NC;               /* 0..31, 4 slots each */
        const unsigned sigval = base + 2u + (unsigned)c;
        float4 ga = make_float4(0.f,0.f,0.f,0.f);
        float4 gb = ga, gc = ga;
        #pragma unroll
        for (int k=0;k<4;k++){
          const float* mp = (const float*)&g_part[((c+1)*NB + l*4 + k)*3];
          while (ld_acq((const unsigned*)(mp+11)) < sigval) npause();
          float4 pa = ldcg4((const float4*)mp);
          float4 pb = ldcg4((const float4*)mp + 1);
          float4 pcv= ldcg4((const float4*)mp + 2);
          f4add(ga, pa); f4add(gb, pb);
          gc.x += pcv.x; gc.y += pcv.y; gc.z += pcv.z;
        }
        #pragma unroll
        for (int o=16;o>0;o>>=1) SHFL11S(o);
        if (tid == NC){ s_wB[0]=ga; s_wB[1]=gb; s_wB[2]=gc; }
      }
      BAR2();
    }
  }

  __syncthreads();
  if (tid == 0) st_rel(&g_sig[bid], base + 1000u);
}

extern "C" void kernel_launch(void* const* d_in, const int* in_sizes, int n_in,
                              void* d_out, int out_size)
{
  (void)in_sizes; (void)n_in; (void)out_size;
  ipls_kernel<<<NB, NTH>>>(
      (const float*)d_in[0],  (const float*)d_in[1],
      (const float*)d_in[2],  (const float*)d_in[3],
      (const float*)d_in[4],  (const float*)d_in[5],
      (const float*)d_in[6],  (const float*)d_in[7],
      (const float*)d_in[8],  (const float*)d_in[9],
      (const int*)  d_in[10], (float*)d_out);
}